// round 2
// baseline (speedup 1.0000x reference)
#include <cuda_runtime.h>
#include <math.h>

// Problem constants
constexpr int BATCH = 4;
constexpr int CH    = 256;
constexpr int SPA   = 4096;       // H*W = 64*64
constexpr int NGRP  = 8;
constexpr int CPG   = CH / NGRP;  // 32 channels per group
constexpr int NH    = 4;
constexpr int HD    = CH / NH;    // 64
constexpr float EPS = 1e-5f;
constexpr float SCALE = 0.125f;   // 64^-0.5

constexpr int GRP_ELEMS = CPG * SPA;   // 131072 elements per (b,g)
constexpr int PARTS = 32;              // partial blocks per group

// Scratch (device globals: no allocation allowed)
__device__ float g_xn  [(size_t)BATCH * CH  * SPA];   // 16 MB  groupnorm output
__device__ float g_qkv [(size_t)BATCH * 3*CH * SPA];  // 48 MB  qkv
__device__ float g_ao  [(size_t)BATCH * CH  * SPA];   // 16 MB  attention output
__device__ float g_part[BATCH * NGRP][PARTS][2];      // partial sums
__device__ float g_mean[BATCH * NGRP];
__device__ float g_rinv[BATCH * NGRP];

// ---------------------------------------------------------------------------
// GroupNorm stage 1: per-(group,part) partial sum / sumsq
// ---------------------------------------------------------------------------
__global__ __launch_bounds__(256) void k_gn_part(const float* __restrict__ x) {
    int part = blockIdx.x & (PARTS - 1);
    int bg   = blockIdx.x / PARTS;
    const float4* base = reinterpret_cast<const float4*>(x + (size_t)bg * GRP_ELEMS)
                         + (size_t)part * (GRP_ELEMS / PARTS / 4);
    const int n4 = GRP_ELEMS / PARTS / 4;   // 1024 float4 per part

    float s = 0.f, s2 = 0.f;
    for (int i = threadIdx.x; i < n4; i += 256) {
        float4 v = base[i];
        s  += v.x + v.y + v.z + v.w;
        s2 += v.x*v.x + v.y*v.y + v.z*v.z + v.w*v.w;
    }
    // block reduce (8 warps)
    __shared__ float sh[16];
    for (int o = 16; o; o >>= 1) {
        s  += __shfl_xor_sync(0xffffffffu, s,  o);
        s2 += __shfl_xor_sync(0xffffffffu, s2, o);
    }
    if ((threadIdx.x & 31) == 0) {
        int w = threadIdx.x >> 5;
        sh[w*2] = s; sh[w*2+1] = s2;
    }
    __syncthreads();
    if (threadIdx.x == 0) {
        float a = 0.f, b = 0.f;
        #pragma unroll
        for (int i = 0; i < 8; i++) { a += sh[i*2]; b += sh[i*2+1]; }
        g_part[bg][part][0] = a;
        g_part[bg][part][1] = b;
    }
}

// ---------------------------------------------------------------------------
// GroupNorm stage 2: finalize mean / rsqrt(var+eps). 32 groups, 1 block.
// ---------------------------------------------------------------------------
__global__ void k_gn_final() {
    int g = threadIdx.x;
    if (g >= BATCH * NGRP) return;
    float s = 0.f, s2 = 0.f;
    #pragma unroll
    for (int p = 0; p < PARTS; p++) { s += g_part[g][p][0]; s2 += g_part[g][p][1]; }
    const float invN = 1.0f / (float)GRP_ELEMS;
    float mean = s * invN;
    float var  = s2 * invN - mean * mean;
    g_mean[g] = mean;
    g_rinv[g] = rsqrtf(var + EPS);
}

// ---------------------------------------------------------------------------
// GroupNorm stage 3: normalize elementwise (vectorized)
// ---------------------------------------------------------------------------
__global__ __launch_bounds__(256) void k_gn_norm(const float* __restrict__ x,
                                                 const float* __restrict__ gamma,
                                                 const float* __restrict__ beta) {
    int idx4 = blockIdx.x * 256 + threadIdx.x;
    if (idx4 >= (BATCH * CH * SPA) / 4) return;
    int idx = idx4 * 4;
    int c  = (idx >> 12) & (CH - 1);   // SPA = 4096 = 2^12
    int bg = idx >> 17;                // GRP_ELEMS = 2^17
    float mean = g_mean[bg], rinv = g_rinv[bg];
    float ga = gamma[c] * rinv;
    float be = beta[c] - mean * ga;
    float4 v = reinterpret_cast<const float4*>(x)[idx4];
    float4 o;
    o.x = v.x * ga + be; o.y = v.y * ga + be;
    o.z = v.z * ga + be; o.w = v.w * ga + be;
    reinterpret_cast<float4*>(g_xn)[idx4] = o;
}

// ---------------------------------------------------------------------------
// Tiled SGEMM: Y[b][o][s] = sum_c W[o][c] * X[b][c][s] + bias[o] (+ resid)
// Tile 64x64, K-step 16, 16x16 threads, 4x4 per thread.
// ---------------------------------------------------------------------------
template<bool RESID>
__global__ __launch_bounds__(256) void k_gemm(const float* __restrict__ Wm,
                                              const float* __restrict__ bias,
                                              const float* __restrict__ X,
                                              float* __restrict__ Y,
                                              const float* __restrict__ resid,
                                              int M) {
    __shared__ float As[16][68];   // As[k][m]   (W tile, transposed)
    __shared__ float Bs[16][64];   // Bs[k][n]   (X tile)

    const int b  = blockIdx.z;
    const int o0 = blockIdx.y * 64;
    const int s0 = blockIdx.x * 64;
    const int tx = threadIdx.x, ty = threadIdx.y;
    const int tid = ty * 16 + tx;
    const float* Xb = X + (size_t)b * CH * SPA;

    float acc[4][4] = {};

    for (int k0 = 0; k0 < CH; k0 += 16) {
        // load W tile: W[o0+op][k0+cp] -> As[cp][op]
        {
            int cp = tid & 15;
            int ob = (tid >> 4) * 4;
            #pragma unroll
            for (int r = 0; r < 4; r++)
                As[cp][ob + r] = Wm[(size_t)(o0 + ob + r) * CH + k0 + cp];
        }
        // load X tile: X[k0+kk][s0+ss] -> Bs[kk][ss]
        {
            int ss = tid & 63;
            int kb = tid >> 6;   // 0..3
            #pragma unroll
            for (int r = 0; r < 4; r++) {
                int kk = kb * 4 + r;
                Bs[kk][ss] = Xb[(size_t)(k0 + kk) * SPA + s0 + ss];
            }
        }
        __syncthreads();
        #pragma unroll
        for (int kk = 0; kk < 16; kk++) {
            float4 a  = *reinterpret_cast<const float4*>(&As[kk][ty * 4]);
            float4 bb = *reinterpret_cast<const float4*>(&Bs[kk][tx * 4]);
            float av[4] = {a.x, a.y, a.z, a.w};
            float bv[4] = {bb.x, bb.y, bb.z, bb.w};
            #pragma unroll
            for (int i = 0; i < 4; i++)
                #pragma unroll
                for (int j = 0; j < 4; j++)
                    acc[i][j] += av[i] * bv[j];
        }
        __syncthreads();
    }

    #pragma unroll
    for (int i = 0; i < 4; i++) {
        int o = o0 + ty * 4 + i;
        float bval = bias[o];
        size_t off = ((size_t)b * M + o) * SPA + s0 + tx * 4;
        float4 r;
        r.x = acc[i][0] + bval; r.y = acc[i][1] + bval;
        r.z = acc[i][2] + bval; r.w = acc[i][3] + bval;
        if (RESID) {
            float4 xr = *reinterpret_cast<const float4*>(&resid[off]);
            r.x += xr.x; r.y += xr.y; r.z += xr.z; r.w += xr.w;
        }
        *reinterpret_cast<float4*>(&Y[off]) = r;
    }
}

// ---------------------------------------------------------------------------
// Flash attention (fp32, SIMT). One block = one (b,h) x 64-query tile.
// Iterates 64-key tiles with online softmax. 16x16 threads, 4q x 4 per thread.
// ---------------------------------------------------------------------------
__global__ __launch_bounds__(256) void k_attn() {
    const int bh = blockIdx.y;
    const int b  = bh >> 2;       // NH = 4
    const int h  = bh & 3;
    const float* qb = g_qkv + ((size_t)b * 3 * CH + h * HD) * SPA;
    const float* kb = qb + (size_t)CH * SPA;
    const float* vb = qb + (size_t)2 * CH * SPA;
    const int q0 = blockIdx.x * 64;
    const int tid = threadIdx.x;
    const int tx = tid & 15, ty = tid >> 4;

    extern __shared__ float sm[];
    float* Qs = sm;               // [64][68]  Qs[d][i]
    float* Ks = Qs + 64 * 68;     // [64][68]  Ks[d][j]
    float* Vs = Ks + 64 * 68;     // [64][68]  Vs[j][d]  (transposed)
    float* Ps = Vs + 64 * 68;     // [64][68]  Ps[i][j]

    // load Q tile
    for (int idx = tid; idx < 64 * 64; idx += 256) {
        int d = idx >> 6, i = idx & 63;
        Qs[d * 68 + i] = qb[(size_t)d * SPA + q0 + i];
    }

    float m_run[4], l_run[4], o_acc[4][4];
    #pragma unroll
    for (int i = 0; i < 4; i++) {
        m_run[i] = -1e30f; l_run[i] = 0.f;
        #pragma unroll
        for (int u = 0; u < 4; u++) o_acc[i][u] = 0.f;
    }

    for (int t0 = 0; t0 < SPA; t0 += 64) {
        // load K [d][j] and V transposed [j][d]
        for (int idx = tid; idx < 64 * 64; idx += 256) {
            int d = idx >> 6, j = idx & 63;
            float kv = kb[(size_t)d * SPA + t0 + j];
            float vv = vb[(size_t)d * SPA + t0 + j];
            Ks[d * 68 + j] = kv;
            Vs[j * 68 + d] = vv;
        }
        __syncthreads();

        // scores: acc[i][j] = sum_d Qs[d][ty4+i] * Ks[d][tx4+j]
        float acc[4][4] = {};
        #pragma unroll 8
        for (int d = 0; d < 64; d++) {
            float4 qv = *reinterpret_cast<const float4*>(&Qs[d * 68 + ty * 4]);
            float4 kv = *reinterpret_cast<const float4*>(&Ks[d * 68 + tx * 4]);
            float qa[4] = {qv.x, qv.y, qv.z, qv.w};
            float ka[4] = {kv.x, kv.y, kv.z, kv.w};
            #pragma unroll
            for (int i = 0; i < 4; i++)
                #pragma unroll
                for (int j = 0; j < 4; j++)
                    acc[i][j] += qa[i] * ka[j];
        }

        // online softmax per query row (rows replicated across the 16 tx lanes)
        #pragma unroll
        for (int i = 0; i < 4; i++) {
            float s_[4];
            #pragma unroll
            for (int j = 0; j < 4; j++) s_[j] = acc[i][j] * SCALE;
            float mx = fmaxf(fmaxf(s_[0], s_[1]), fmaxf(s_[2], s_[3]));
            #pragma unroll
            for (int o = 1; o < 16; o <<= 1)
                mx = fmaxf(mx, __shfl_xor_sync(0xffffffffu, mx, o, 16));
            float mnew = fmaxf(m_run[i], mx);
            float p[4], rs = 0.f;
            #pragma unroll
            for (int j = 0; j < 4; j++) { p[j] = __expf(s_[j] - mnew); rs += p[j]; }
            #pragma unroll
            for (int o = 1; o < 16; o <<= 1)
                rs += __shfl_xor_sync(0xffffffffu, rs, o, 16);
            float alpha = __expf(m_run[i] - mnew);
            l_run[i] = l_run[i] * alpha + rs;
            m_run[i] = mnew;
            #pragma unroll
            for (int u = 0; u < 4; u++) o_acc[i][u] *= alpha;
            float4 pv = {p[0], p[1], p[2], p[3]};
            *reinterpret_cast<float4*>(&Ps[(ty * 4 + i) * 68 + tx * 4]) = pv;
        }
        __syncthreads();

        // PV: o_acc[i][u] += sum_j Ps[ty4+i][j] * Vs[j][tx4+u]
        #pragma unroll 4
        for (int j0 = 0; j0 < 64; j0 += 4) {
            float4 pr[4];
            #pragma unroll
            for (int i = 0; i < 4; i++)
                pr[i] = *reinterpret_cast<const float4*>(&Ps[(ty * 4 + i) * 68 + j0]);
            #pragma unroll
            for (int jj = 0; jj < 4; jj++) {
                float4 vv = *reinterpret_cast<const float4*>(&Vs[(j0 + jj) * 68 + tx * 4]);
                #pragma unroll
                for (int i = 0; i < 4; i++) {
                    float pij = (jj == 0) ? pr[i].x : (jj == 1) ? pr[i].y :
                                (jj == 2) ? pr[i].z : pr[i].w;
                    o_acc[i][0] += pij * vv.x;
                    o_acc[i][1] += pij * vv.y;
                    o_acc[i][2] += pij * vv.z;
                    o_acc[i][3] += pij * vv.w;
                }
            }
        }
        __syncthreads();
    }

    // stage normalized output through Ps for coalesced write: Ps[qi][dd]
    #pragma unroll
    for (int i = 0; i < 4; i++) {
        float inv = 1.0f / l_run[i];
        float4 r = {o_acc[i][0] * inv, o_acc[i][1] * inv,
                    o_acc[i][2] * inv, o_acc[i][3] * inv};
        *reinterpret_cast<float4*>(&Ps[(ty * 4 + i) * 68 + tx * 4]) = r;
    }
    __syncthreads();
    float* ob = g_ao + ((size_t)b * CH + h * HD) * SPA + q0;
    for (int idx = tid; idx < 64 * 64; idx += 256) {
        int dd = idx >> 6, j = idx & 63;
        ob[(size_t)dd * SPA + j] = Ps[j * 68 + dd];
    }
}

// ---------------------------------------------------------------------------
extern "C" void kernel_launch(void* const* d_in, const int* in_sizes, int n_in,
                              void* d_out, int out_size) {
    const float* x      = (const float*)d_in[0];
    const float* gamma  = (const float*)d_in[1];
    const float* beta   = (const float*)d_in[2];
    const float* w_qkv  = (const float*)d_in[3];
    const float* b_qkv  = (const float*)d_in[4];
    const float* w_proj = (const float*)d_in[5];
    const float* b_proj = (const float*)d_in[6];
    float* out = (float*)d_out;

    // pointers to device scratch
    float *xn_p, *qkv_p, *ao_p;
    cudaGetSymbolAddress((void**)&xn_p,  g_xn);
    cudaGetSymbolAddress((void**)&qkv_p, g_qkv);
    cudaGetSymbolAddress((void**)&ao_p,  g_ao);

    const size_t attn_smem = 4 * 64 * 68 * sizeof(float);  // ~68 KB
    cudaFuncSetAttribute(k_attn, cudaFuncAttributeMaxDynamicSharedMemorySize,
                         (int)attn_smem);

    // GroupNorm
    k_gn_part <<<BATCH * NGRP * PARTS, 256>>>(x);
    k_gn_final<<<1, 32>>>();
    k_gn_norm <<<(BATCH * CH * SPA) / 4 / 256, 256>>>(x, gamma, beta);

    // QKV GEMM: M=768
    {
        dim3 grid(SPA / 64, (3 * CH) / 64, BATCH);
        dim3 blk(16, 16);
        k_gemm<false><<<grid, blk>>>(w_qkv, b_qkv, xn_p, qkv_p, nullptr, 3 * CH);
    }

    // Flash attention
    {
        dim3 grid(SPA / 64, BATCH * NH);
        k_attn<<<grid, 256, attn_smem>>>();
    }

    // Proj GEMM + residual: M=256
    {
        dim3 grid(SPA / 64, CH / 64, BATCH);
        dim3 blk(16, 16);
        k_gemm<true><<<grid, blk>>>(w_proj, b_proj, ao_p, out, x, CH);
    }
}

// round 4
// speedup vs baseline: 2.5045x; 2.5045x over previous
#include <cuda_runtime.h>
#include <cstdint>
#include <math.h>

// Problem constants
constexpr int BATCH = 4;
constexpr int CH    = 256;
constexpr int SPA   = 4096;       // H*W = 64*64
constexpr int NGRP  = 8;
constexpr int CPG   = CH / NGRP;  // 32
constexpr int NH    = 4;
constexpr int HD    = CH / NH;    // 64
constexpr float EPS = 1e-5f;
constexpr float SCALE = 0.125f;   // 64^-0.5

constexpr int GRP_ELEMS = CPG * SPA;   // 131072
constexpr int PARTS = 32;

// Scratch (device globals: no allocation allowed)
__device__ float g_xn  [(size_t)BATCH * CH  * SPA];   // 16 MB
__device__ float g_qkv [(size_t)BATCH * 3*CH * SPA];  // 48 MB
__device__ float g_ao  [(size_t)BATCH * CH  * SPA];   // 16 MB
__device__ float g_part[BATCH * NGRP][PARTS][2];
__device__ float g_mean[BATCH * NGRP];
__device__ float g_rinv[BATCH * NGRP];

// ---------------------------------------------------------------------------
// Helpers: tf32 convert + m16n8k8 tf32 mma
// ---------------------------------------------------------------------------
__device__ __forceinline__ uint32_t f2tf32(float x) {
    uint32_t y; asm("cvt.rna.tf32.f32 %0, %1;" : "=r"(y) : "f"(x)); return y;
}

__device__ __forceinline__ void mma_tf32(float* d, const uint32_t* a,
                                         const uint32_t* b) {
    asm volatile(
        "mma.sync.aligned.m16n8k8.row.col.f32.tf32.tf32.f32 "
        "{%0,%1,%2,%3}, {%4,%5,%6,%7}, {%8,%9}, {%0,%1,%2,%3};\n"
        : "+f"(d[0]), "+f"(d[1]), "+f"(d[2]), "+f"(d[3])
        : "r"(a[0]), "r"(a[1]), "r"(a[2]), "r"(a[3]), "r"(b[0]), "r"(b[1]));
}

// ---------------------------------------------------------------------------
// GroupNorm stage 1: partial sums
// ---------------------------------------------------------------------------
__global__ __launch_bounds__(256) void k_gn_part(const float* __restrict__ x) {
    int part = blockIdx.x & (PARTS - 1);
    int bg   = blockIdx.x / PARTS;
    const float4* base = reinterpret_cast<const float4*>(x + (size_t)bg * GRP_ELEMS)
                         + (size_t)part * (GRP_ELEMS / PARTS / 4);
    const int n4 = GRP_ELEMS / PARTS / 4;

    float s = 0.f, s2 = 0.f;
    for (int i = threadIdx.x; i < n4; i += 256) {
        float4 v = base[i];
        s  += v.x + v.y + v.z + v.w;
        s2 += v.x*v.x + v.y*v.y + v.z*v.z + v.w*v.w;
    }
    __shared__ float sh[16];
    for (int o = 16; o; o >>= 1) {
        s  += __shfl_xor_sync(0xffffffffu, s,  o);
        s2 += __shfl_xor_sync(0xffffffffu, s2, o);
    }
    if ((threadIdx.x & 31) == 0) {
        int w = threadIdx.x >> 5;
        sh[w*2] = s; sh[w*2+1] = s2;
    }
    __syncthreads();
    if (threadIdx.x == 0) {
        float a = 0.f, b = 0.f;
        #pragma unroll
        for (int i = 0; i < 8; i++) { a += sh[i*2]; b += sh[i*2+1]; }
        g_part[bg][part][0] = a;
        g_part[bg][part][1] = b;
    }
}

__global__ void k_gn_final() {
    int g = threadIdx.x;
    if (g >= BATCH * NGRP) return;
    float s = 0.f, s2 = 0.f;
    #pragma unroll
    for (int p = 0; p < PARTS; p++) { s += g_part[g][p][0]; s2 += g_part[g][p][1]; }
    const float invN = 1.0f / (float)GRP_ELEMS;
    float mean = s * invN;
    float var  = s2 * invN - mean * mean;
    g_mean[g] = mean;
    g_rinv[g] = rsqrtf(var + EPS);
}

__global__ __launch_bounds__(256) void k_gn_norm(const float* __restrict__ x,
                                                 const float* __restrict__ gamma,
                                                 const float* __restrict__ beta) {
    int idx4 = blockIdx.x * 256 + threadIdx.x;
    if (idx4 >= (BATCH * CH * SPA) / 4) return;
    int idx = idx4 * 4;
    int c  = (idx >> 12) & (CH - 1);
    int bg = idx >> 17;
    float mean = g_mean[bg], rinv = g_rinv[bg];
    float ga = gamma[c] * rinv;
    float be = beta[c] - mean * ga;
    float4 v = reinterpret_cast<const float4*>(x)[idx4];
    float4 o;
    o.x = v.x * ga + be; o.y = v.y * ga + be;
    o.z = v.z * ga + be; o.w = v.w * ga + be;
    reinterpret_cast<float4*>(g_xn)[idx4] = o;
}

// ---------------------------------------------------------------------------
// tf32 tensor-core GEMM: Y[b][o][s] = sum_c W[o][c] * X[b][c][s] + bias (+resid)
// Block tile 128x128, K-step 32, 8 warps (4M x 2N). Warps own disjoint output
// tiles with the full K reduction, so no cross-warp stats needed.
// ---------------------------------------------------------------------------
template<bool RESID>
__global__ __launch_bounds__(256, 2) void k_gemm(const float* __restrict__ Wm,
                                                 const float* __restrict__ bias,
                                                 const float* __restrict__ X,
                                                 float* __restrict__ Y,
                                                 const float* __restrict__ resid,
                                                 int M) {
    __shared__ uint32_t As[128 * 36];   // As[m][k], pad 36
    __shared__ uint32_t Bs[32 * 132];   // Bs[k][n], pad 132

    const int b  = blockIdx.z;
    const int o0 = blockIdx.y * 128;
    const int s0 = blockIdx.x * 128;
    const int tid = threadIdx.x, lane = tid & 31, wid = tid >> 5;
    const int wm = wid & 3, wn = wid >> 2;
    const float* Xb = X + (size_t)b * CH * SPA;

    float acc[2][8][4] = {};

    for (int k0 = 0; k0 < CH; k0 += 32) {
        #pragma unroll
        for (int r = 0; r < 4; r++) {
            int i = tid + r * 256;
            int row = i >> 3, kq = (i & 7) * 4;
            float4 w4 = *reinterpret_cast<const float4*>(
                            Wm + (size_t)(o0 + row) * CH + k0 + kq);
            uint4 wa = {f2tf32(w4.x), f2tf32(w4.y), f2tf32(w4.z), f2tf32(w4.w)};
            *reinterpret_cast<uint4*>(&As[row * 36 + kq]) = wa;
            int kr = i >> 5, sq = (i & 31) * 4;
            float4 x4 = *reinterpret_cast<const float4*>(
                            Xb + (size_t)(k0 + kr) * SPA + s0 + sq);
            uint4 xb = {f2tf32(x4.x), f2tf32(x4.y), f2tf32(x4.z), f2tf32(x4.w)};
            *reinterpret_cast<uint4*>(&Bs[kr * 132 + sq]) = xb;
        }
        __syncthreads();

        #pragma unroll
        for (int kk = 0; kk < 32; kk += 8) {
            uint32_t a[2][4], bf[8][2];
            #pragma unroll
            for (int mt = 0; mt < 2; mt++) {
                int rb = wm * 32 + mt * 16 + (lane >> 2);
                a[mt][0] = As[rb * 36 + kk + (lane & 3)];
                a[mt][1] = As[(rb + 8) * 36 + kk + (lane & 3)];
                a[mt][2] = As[rb * 36 + kk + (lane & 3) + 4];
                a[mt][3] = As[(rb + 8) * 36 + kk + (lane & 3) + 4];
            }
            #pragma unroll
            for (int nt = 0; nt < 8; nt++) {
                int nb = wn * 64 + nt * 8 + (lane >> 2);
                bf[nt][0] = Bs[(kk + (lane & 3)) * 132 + nb];
                bf[nt][1] = Bs[(kk + (lane & 3) + 4) * 132 + nb];
            }
            #pragma unroll
            for (int mt = 0; mt < 2; mt++)
                #pragma unroll
                for (int nt = 0; nt < 8; nt++)
                    mma_tf32(acc[mt][nt], a[mt], bf[nt]);
        }
        __syncthreads();
    }

    #pragma unroll
    for (int mt = 0; mt < 2; mt++) {
        int row0 = o0 + wm * 32 + mt * 16 + (lane >> 2);
        float bv0 = bias[row0], bv1 = bias[row0 + 8];
        #pragma unroll
        for (int nt = 0; nt < 8; nt++) {
            int col = s0 + wn * 64 + nt * 8 + 2 * (lane & 3);
            size_t off0 = ((size_t)b * M + row0) * SPA + col;
            size_t off1 = ((size_t)b * M + row0 + 8) * SPA + col;
            float2 r0 = {acc[mt][nt][0] + bv0, acc[mt][nt][1] + bv0};
            float2 r1 = {acc[mt][nt][2] + bv1, acc[mt][nt][3] + bv1};
            if (RESID) {
                float2 x0 = *reinterpret_cast<const float2*>(&resid[off0]);
                float2 x1 = *reinterpret_cast<const float2*>(&resid[off1]);
                r0.x += x0.x; r0.y += x0.y;
                r1.x += x1.x; r1.y += x1.y;
            }
            *reinterpret_cast<float2*>(&Y[off0]) = r0;
            *reinterpret_cast<float2*>(&Y[off1]) = r1;
        }
    }
}

// ---------------------------------------------------------------------------
// Flash attention, tf32 tensor cores — FIXED warp decomposition.
// Block = (b,h) x 128-query tile; 8 warps; warp w owns query rows
// [w*16, w*16+16) and the FULL 64-key width, so softmax stats are complete
// within the warp (no cross-warp normalization mixing).
// ---------------------------------------------------------------------------
constexpr int QT = 128;
constexpr int KT = 64;

__global__ __launch_bounds__(256, 2) void k_attn() {
    const int bh = blockIdx.y;
    const int b  = bh >> 2;
    const int h  = bh & 3;
    const float* qb = g_qkv + ((size_t)b * 3 * CH + h * HD) * SPA;
    const float* kb = qb + (size_t)CH * SPA;
    const float* vb = qb + (size_t)2 * CH * SPA;
    const int q0 = blockIdx.x * QT;
    const int tid = threadIdx.x, lane = tid & 31, w = tid >> 5;

    extern __shared__ uint32_t sm[];
    uint32_t* Qs = sm;                  // [128][68]  Qs[q][dd]   (tf32)
    uint32_t* Ks = Qs + 128 * 68;       // [64][68]   Ks[key][dd]
    uint32_t* Vs = Ks + 64 * 68;        // [64][68]   Vs[dd][key]
    uint32_t* Ps = Vs + 64 * 68;        // [128][68]  Ps[q][key] (warp-private rows)

    // load Q tile transposed: [d][s] -> Qs[q][dd]
    for (int i = tid; i < 64 * 32; i += 256) {
        int dd = i >> 5, sq = (i & 31) * 4;
        float4 v = *reinterpret_cast<const float4*>(qb + (size_t)dd * SPA + q0 + sq);
        Qs[(sq + 0) * 68 + dd] = f2tf32(v.x);
        Qs[(sq + 1) * 68 + dd] = f2tf32(v.y);
        Qs[(sq + 2) * 68 + dd] = f2tf32(v.z);
        Qs[(sq + 3) * 68 + dd] = f2tf32(v.w);
    }

    float m2[2] = {-INFINITY, -INFINITY};
    float l [2] = {0.f, 0.f};
    float o_acc[8][4] = {};                // [d-tile][frag]
    const float CF = SCALE * 1.44269504f;  // scale * log2(e)
    const int rq = w * 16 + (lane >> 2);   // this thread's base query row

    for (int t0 = 0; t0 < SPA; t0 += KT) {
        __syncthreads();   // prev iteration's PV reads of Ks/Vs complete
        // load K (transposed->[key][d]) and V ([d][key]) tiles
        for (int i = tid; i < 64 * 16; i += 256) {
            int dd = i >> 4, sq = (i & 15) * 4;
            float4 kv = *reinterpret_cast<const float4*>(kb + (size_t)dd * SPA + t0 + sq);
            Ks[(sq + 0) * 68 + dd] = f2tf32(kv.x);
            Ks[(sq + 1) * 68 + dd] = f2tf32(kv.y);
            Ks[(sq + 2) * 68 + dd] = f2tf32(kv.z);
            Ks[(sq + 3) * 68 + dd] = f2tf32(kv.w);
            float4 vv = *reinterpret_cast<const float4*>(vb + (size_t)dd * SPA + t0 + sq);
            uint4 vq = {f2tf32(vv.x), f2tf32(vv.y), f2tf32(vv.z), f2tf32(vv.w)};
            *reinterpret_cast<uint4*>(&Vs[dd * 68 + sq]) = vq;
        }
        __syncthreads();

        // S = Q K^T : warp tile M=16 q, N=64 keys, K=64 d
        float sacc[8][4] = {};
        #pragma unroll
        for (int kk = 0; kk < 64; kk += 8) {
            uint32_t a[4];
            a[0] = Qs[rq * 68 + kk + (lane & 3)];
            a[1] = Qs[(rq + 8) * 68 + kk + (lane & 3)];
            a[2] = Qs[rq * 68 + kk + (lane & 3) + 4];
            a[3] = Qs[(rq + 8) * 68 + kk + (lane & 3) + 4];
            #pragma unroll
            for (int nt = 0; nt < 8; nt++) {
                int nb = nt * 8 + (lane >> 2);
                uint32_t bf[2] = {Ks[nb * 68 + kk + (lane & 3)],
                                  Ks[nb * 68 + kk + (lane & 3) + 4]};
                mma_tf32(sacc[nt], a, bf);
            }
        }

        // online softmax — full 64-key row within this warp
        #pragma unroll
        for (int rh = 0; rh < 2; rh++) {
            float mx = -1e30f;
            #pragma unroll
            for (int nt = 0; nt < 8; nt++)
                mx = fmaxf(mx, fmaxf(sacc[nt][rh*2], sacc[nt][rh*2+1]));
            mx *= CF;
            mx = fmaxf(mx, __shfl_xor_sync(0xffffffffu, mx, 1));
            mx = fmaxf(mx, __shfl_xor_sync(0xffffffffu, mx, 2));
            float mnew = fmaxf(m2[rh], mx);
            float alpha = exp2f(m2[rh] - mnew);
            m2[rh] = mnew;
            int row = w * 16 + rh * 8 + (lane >> 2);
            float rs = 0.f;
            #pragma unroll
            for (int nt = 0; nt < 8; nt++) {
                float p0 = exp2f(sacc[nt][rh*2]   * CF - mnew);
                float p1 = exp2f(sacc[nt][rh*2+1] * CF - mnew);
                rs += p0 + p1;
                int col = nt * 8 + 2 * (lane & 3);
                Ps[row * 68 + col]     = f2tf32(p0);
                Ps[row * 68 + col + 1] = f2tf32(p1);
                o_acc[nt][rh*2]   *= alpha;   // rescale existing O (all d-tiles)
                o_acc[nt][rh*2+1] *= alpha;
            }
            rs += __shfl_xor_sync(0xffffffffu, rs, 1);
            rs += __shfl_xor_sync(0xffffffffu, rs, 2);
            l[rh] = l[rh] * alpha + rs;
        }
        __syncwarp();   // warp-private Ps rows: warp-level sync suffices

        // O += P V : warp tile M=16 q, N=64 d, K=64 keys
        #pragma unroll
        for (int kk = 0; kk < 64; kk += 8) {
            uint32_t a[4];
            a[0] = Ps[rq * 68 + kk + (lane & 3)];
            a[1] = Ps[(rq + 8) * 68 + kk + (lane & 3)];
            a[2] = Ps[rq * 68 + kk + (lane & 3) + 4];
            a[3] = Ps[(rq + 8) * 68 + kk + (lane & 3) + 4];
            #pragma unroll
            for (int nt = 0; nt < 8; nt++) {
                int nb = nt * 8 + (lane >> 2);
                uint32_t bf[2] = {Vs[nb * 68 + kk + (lane & 3)],
                                  Vs[nb * 68 + kk + (lane & 3) + 4]};
                mma_tf32(o_acc[nt], a, bf);
            }
        }
    }

    // normalize + write out: g_ao[b][h*64+dd][q0+qr]
    float* ob = g_ao + ((size_t)b * CH + h * HD) * SPA + q0;
    #pragma unroll
    for (int rh = 0; rh < 2; rh++) {
        float inv = 1.0f / l[rh];
        int qr = w * 16 + rh * 8 + (lane >> 2);
        #pragma unroll
        for (int nt = 0; nt < 8; nt++) {
            int dd = nt * 8 + 2 * (lane & 3);
            ob[(size_t)dd * SPA + qr]       = o_acc[nt][rh*2]   * inv;
            ob[(size_t)(dd + 1) * SPA + qr] = o_acc[nt][rh*2+1] * inv;
        }
    }
}

// ---------------------------------------------------------------------------
extern "C" void kernel_launch(void* const* d_in, const int* in_sizes, int n_in,
                              void* d_out, int out_size) {
    const float* x      = (const float*)d_in[0];
    const float* gamma  = (const float*)d_in[1];
    const float* beta   = (const float*)d_in[2];
    const float* w_qkv  = (const float*)d_in[3];
    const float* b_qkv  = (const float*)d_in[4];
    const float* w_proj = (const float*)d_in[5];
    const float* b_proj = (const float*)d_in[6];
    float* out = (float*)d_out;

    float *xn_p, *qkv_p, *ao_p;
    cudaGetSymbolAddress((void**)&xn_p,  g_xn);
    cudaGetSymbolAddress((void**)&qkv_p, g_qkv);
    cudaGetSymbolAddress((void**)&ao_p,  g_ao);

    const size_t attn_smem = (size_t)(128*68 + 64*68 + 64*68 + 128*68) * 4;  // 104448
    cudaFuncSetAttribute(k_attn, cudaFuncAttributeMaxDynamicSharedMemorySize,
                         (int)attn_smem);

    // GroupNorm
    k_gn_part <<<BATCH * NGRP * PARTS, 256>>>(x);
    k_gn_final<<<1, 32>>>();
    k_gn_norm <<<(BATCH * CH * SPA) / 4 / 256, 256>>>(x, gamma, beta);

    // QKV GEMM (M = 768)
    {
        dim3 grid(SPA / 128, (3 * CH) / 128, BATCH);
        k_gemm<false><<<grid, 256>>>(w_qkv, b_qkv, xn_p, qkv_p, nullptr, 3 * CH);
    }

    // Flash attention
    {
        dim3 grid(SPA / QT, BATCH * NH);
        k_attn<<<grid, 256, attn_smem>>>();
    }

    // Proj GEMM + residual (M = 256)
    {
        dim3 grid(SPA / 128, CH / 128, BATCH);
        k_gemm<true><<<grid, 256>>>(w_proj, b_proj, ao_p, out, x, CH);
    }
}

// round 5
// speedup vs baseline: 6.3706x; 2.5436x over previous
#include <cuda_runtime.h>
#include <cuda_bf16.h>
#include <cstdint>
#include <math.h>

// Problem constants
constexpr int BATCH = 4;
constexpr int CH    = 256;
constexpr int SPA   = 4096;       // H*W
constexpr int NGRP  = 8;
constexpr int CPG   = CH / NGRP;  // 32
constexpr int NH    = 4;
constexpr int HD    = CH / NH;    // 64
constexpr float EPS = 1e-5f;
constexpr float SCALE = 0.125f;

constexpr int GRP_ELEMS = CPG * SPA;
constexpr int PARTS = 32;

// Scratch (device globals; bf16 intermediates)
__device__ __nv_bfloat16 g_xn [(size_t)BATCH * CH  * SPA];   // 8 MB
__device__ __nv_bfloat16 g_qkv[(size_t)BATCH * 3*CH * SPA];  // 24 MB
__device__ __nv_bfloat16 g_ao [(size_t)BATCH * CH  * SPA];   // 8 MB
__device__ float g_part[BATCH * NGRP][PARTS][2];
__device__ float g_mean[BATCH * NGRP];
__device__ float g_rinv[BATCH * NGRP];

// ---------------------------------------------------------------------------
// Helpers
// ---------------------------------------------------------------------------
__device__ __forceinline__ uint32_t smem_u32(const void* p) {
    return (uint32_t)__cvta_generic_to_shared(p);
}

__device__ __forceinline__ uint32_t packbf(float lo, float hi) {
    __nv_bfloat162 t = __floats2bfloat162_rn(lo, hi);   // .x = lo (low 16 bits)
    return *reinterpret_cast<uint32_t*>(&t);
}

// mma m16n8k16 bf16 -> f32
__device__ __forceinline__ void mma_bf16(float* d, const uint32_t* a,
                                         const uint32_t* b) {
    asm volatile(
        "mma.sync.aligned.m16n8k16.row.col.f32.bf16.bf16.f32 "
        "{%0,%1,%2,%3}, {%4,%5,%6,%7}, {%8,%9}, {%0,%1,%2,%3};\n"
        : "+f"(d[0]), "+f"(d[1]), "+f"(d[2]), "+f"(d[3])
        : "r"(a[0]), "r"(a[1]), "r"(a[2]), "r"(a[3]), "r"(b[0]), "r"(b[1]));
}

__device__ __forceinline__ void ldsm_x4(uint32_t* r, uint32_t addr) {
    asm volatile("ldmatrix.sync.aligned.m8n8.x4.shared.b16 {%0,%1,%2,%3}, [%4];\n"
                 : "=r"(r[0]), "=r"(r[1]), "=r"(r[2]), "=r"(r[3]) : "r"(addr));
}
__device__ __forceinline__ void ldsm_x4_t(uint32_t* r, uint32_t addr) {
    asm volatile("ldmatrix.sync.aligned.m8n8.x4.trans.shared.b16 {%0,%1,%2,%3}, [%4];\n"
                 : "=r"(r[0]), "=r"(r[1]), "=r"(r[2]), "=r"(r[3]) : "r"(addr));
}

// ---------------------------------------------------------------------------
// GroupNorm
// ---------------------------------------------------------------------------
__global__ __launch_bounds__(256) void k_gn_part(const float* __restrict__ x) {
    int part = blockIdx.x & (PARTS - 1);
    int bg   = blockIdx.x / PARTS;
    const float4* base = reinterpret_cast<const float4*>(x + (size_t)bg * GRP_ELEMS)
                         + (size_t)part * (GRP_ELEMS / PARTS / 4);
    const int n4 = GRP_ELEMS / PARTS / 4;

    float s = 0.f, s2 = 0.f;
    for (int i = threadIdx.x; i < n4; i += 256) {
        float4 v = base[i];
        s  += v.x + v.y + v.z + v.w;
        s2 += v.x*v.x + v.y*v.y + v.z*v.z + v.w*v.w;
    }
    __shared__ float sh[16];
    for (int o = 16; o; o >>= 1) {
        s  += __shfl_xor_sync(0xffffffffu, s,  o);
        s2 += __shfl_xor_sync(0xffffffffu, s2, o);
    }
    if ((threadIdx.x & 31) == 0) {
        int w = threadIdx.x >> 5;
        sh[w*2] = s; sh[w*2+1] = s2;
    }
    __syncthreads();
    if (threadIdx.x == 0) {
        float a = 0.f, b = 0.f;
        #pragma unroll
        for (int i = 0; i < 8; i++) { a += sh[i*2]; b += sh[i*2+1]; }
        g_part[bg][part][0] = a;
        g_part[bg][part][1] = b;
    }
}

__global__ void k_gn_final() {
    int g = threadIdx.x;
    if (g >= BATCH * NGRP) return;
    float s = 0.f, s2 = 0.f;
    #pragma unroll
    for (int p = 0; p < PARTS; p++) { s += g_part[g][p][0]; s2 += g_part[g][p][1]; }
    const float invN = 1.0f / (float)GRP_ELEMS;
    float mean = s * invN;
    float var  = s2 * invN - mean * mean;
    g_mean[g] = mean;
    g_rinv[g] = rsqrtf(var + EPS);
}

__global__ __launch_bounds__(256) void k_gn_norm(const float* __restrict__ x,
                                                 const float* __restrict__ gamma,
                                                 const float* __restrict__ beta) {
    int idx4 = blockIdx.x * 256 + threadIdx.x;
    if (idx4 >= (BATCH * CH * SPA) / 4) return;
    int idx = idx4 * 4;
    int c  = (idx >> 12) & (CH - 1);
    int bg = idx >> 17;
    float mean = g_mean[bg], rinv = g_rinv[bg];
    float ga = gamma[c] * rinv;
    float be = beta[c] - mean * ga;
    float4 v = reinterpret_cast<const float4*>(x)[idx4];
    uint2 o;
    o.x = packbf(v.x * ga + be, v.y * ga + be);
    o.y = packbf(v.z * ga + be, v.w * ga + be);
    *reinterpret_cast<uint2*>(&g_xn[idx]) = o;
}

// ---------------------------------------------------------------------------
// bf16 tensor-core GEMM: Y[b][o][s] = sum_c W[o][c]*X[b][c][s] + bias (+resid)
// Block 128x128, K-step 32, 8 warps (4M x 2N), ldmatrix fragments.
// X is bf16 [c][s]; W fp32 (converted on load). OutT: bf16 or fp32(+resid).
// ---------------------------------------------------------------------------
template<bool RESID, typename OT>
__global__ __launch_bounds__(256, 2) void k_gemm(const float* __restrict__ Wm,
                                                 const float* __restrict__ bias,
                                                 const __nv_bfloat16* __restrict__ X,
                                                 OT* __restrict__ Y,
                                                 const float* __restrict__ resid,
                                                 int M) {
    __shared__ __nv_bfloat16 As[128 * 40];   // A[m][k], stride 40 (80B, 16B-mult)
    __shared__ __nv_bfloat16 Bs[32 * 136];   // B[k][n], stride 136 (272B)

    const int b  = blockIdx.z;
    const int o0 = blockIdx.y * 128;
    const int s0 = blockIdx.x * 128;
    const int tid = threadIdx.x, lane = tid & 31, wid = tid >> 5;
    const int wm = wid & 3, wn = wid >> 2;
    const int lrow = lane & 7, lmat = lane >> 3;
    const __nv_bfloat16* Xb = X + (size_t)b * CH * SPA;

    float acc[2][8][4] = {};

    for (int k0 = 0; k0 < CH; k0 += 32) {
        // A: 128 rows x 8 float4 of W -> bf16
        #pragma unroll
        for (int r = 0; r < 4; r++) {
            int i = tid + r * 256;
            int row = i >> 3, kq = (i & 7) * 4;
            float4 w4 = *reinterpret_cast<const float4*>(
                            Wm + (size_t)(o0 + row) * CH + k0 + kq);
            uint2 wp = {packbf(w4.x, w4.y), packbf(w4.z, w4.w)};
            *reinterpret_cast<uint2*>(&As[row * 40 + kq]) = wp;
        }
        // B: 32 rows x 16 uint4 (8 bf16 each), direct copy
        #pragma unroll
        for (int r = 0; r < 2; r++) {
            int i = tid + r * 256;
            int kr = i >> 4, s8 = (i & 15) * 8;
            uint4 xv = *reinterpret_cast<const uint4*>(
                            Xb + (size_t)(k0 + kr) * SPA + s0 + s8);
            *reinterpret_cast<uint4*>(&Bs[kr * 136 + s8]) = xv;
        }
        __syncthreads();

        #pragma unroll
        for (int kk = 0; kk < 32; kk += 16) {
            uint32_t a[2][4];
            #pragma unroll
            for (int mt = 0; mt < 2; mt++) {
                uint32_t ad = smem_u32(&As[(wm*32 + mt*16 + (lmat & 1)*8 + lrow)*40
                                           + kk + (lmat >> 1)*8]);
                ldsm_x4(a[mt], ad);
            }
            #pragma unroll
            for (int ntp = 0; ntp < 8; ntp += 2) {
                uint32_t bf[4];
                uint32_t ad = smem_u32(&Bs[(kk + (lmat & 1)*8 + lrow)*136
                                           + wn*64 + (ntp + (lmat >> 1))*8]);
                ldsm_x4_t(bf, ad);
                #pragma unroll
                for (int mt = 0; mt < 2; mt++) {
                    mma_bf16(acc[mt][ntp],     a[mt], bf);
                    mma_bf16(acc[mt][ntp + 1], a[mt], bf + 2);
                }
            }
        }
        __syncthreads();
    }

    // epilogue
    #pragma unroll
    for (int mt = 0; mt < 2; mt++) {
        int row0 = o0 + wm * 32 + mt * 16 + (lane >> 2);
        float bv0 = bias[row0], bv1 = bias[row0 + 8];
        #pragma unroll
        for (int nt = 0; nt < 8; nt++) {
            int col = s0 + wn * 64 + nt * 8 + 2 * (lane & 3);
            size_t off0 = ((size_t)b * M + row0) * SPA + col;
            size_t off1 = ((size_t)b * M + row0 + 8) * SPA + col;
            float r00 = acc[mt][nt][0] + bv0, r01 = acc[mt][nt][1] + bv0;
            float r10 = acc[mt][nt][2] + bv1, r11 = acc[mt][nt][3] + bv1;
            if (RESID) {
                float2 x0 = *reinterpret_cast<const float2*>(&resid[off0]);
                float2 x1 = *reinterpret_cast<const float2*>(&resid[off1]);
                r00 += x0.x; r01 += x0.y; r10 += x1.x; r11 += x1.y;
            }
            if (sizeof(OT) == 2) {
                uint32_t p0 = packbf(r00, r01), p1 = packbf(r10, r11);
                *reinterpret_cast<uint32_t*>(&Y[off0]) = p0;
                *reinterpret_cast<uint32_t*>(&Y[off1]) = p1;
            } else {
                *reinterpret_cast<float2*>(&Y[off0]) = make_float2(r00, r01);
                *reinterpret_cast<float2*>(&Y[off1]) = make_float2(r10, r11);
            }
        }
    }
}

// ---------------------------------------------------------------------------
// Flash attention, bf16 mma + ldmatrix, P kept in registers.
// Block = (b,h) x 128-query tile; warp w owns q rows [w*16, w*16+16),
// full 64-key width. Q/K/V in natural [d][*] SMEM layout (direct copies).
// ---------------------------------------------------------------------------
constexpr int QT = 128;
constexpr int KT = 64;
constexpr int QS_STR = 136;  // Q row stride (bf16), 272B
constexpr int KV_STR = 72;   // K/V row stride, 144B

__global__ __launch_bounds__(256, 2) void k_attn() {
    __shared__ __nv_bfloat16 Qs[64 * QS_STR];  // [d][q]
    __shared__ __nv_bfloat16 Ks[64 * KV_STR];  // [d][key]
    __shared__ __nv_bfloat16 Vs[64 * KV_STR];  // [d][key]

    const int bh = blockIdx.y;
    const int b  = bh >> 2;
    const int h  = bh & 3;
    const __nv_bfloat16* qb = g_qkv + ((size_t)b * 3 * CH + h * HD) * SPA;
    const __nv_bfloat16* kb = qb + (size_t)CH * SPA;
    const __nv_bfloat16* vb = qb + (size_t)2 * CH * SPA;
    const int q0 = blockIdx.x * QT;
    const int tid = threadIdx.x, lane = tid & 31, w = tid >> 5;
    const int lrow = lane & 7, lmat = lane >> 3;

    // load Q tile: direct [d][q] copy
    #pragma unroll
    for (int r = 0; r < 4; r++) {
        int i = tid + r * 256;
        int dd = i >> 4, q8 = (i & 15) * 8;
        uint4 v = *reinterpret_cast<const uint4*>(qb + (size_t)dd * SPA + q0 + q8);
        *reinterpret_cast<uint4*>(&Qs[dd * QS_STR + q8]) = v;
    }
    __syncthreads();

    // hoist Q fragments (A frag per 16-wide k-step, trans ldmatrix)
    uint32_t qa[4][4];
    #pragma unroll
    for (int kk4 = 0; kk4 < 4; kk4++) {
        uint32_t ad = smem_u32(&Qs[(kk4*16 + (lmat >> 1)*8 + lrow) * QS_STR
                                   + w*16 + (lmat & 1)*8]);
        ldsm_x4_t(qa[kk4], ad);
    }

    float m2[2] = {-INFINITY, -INFINITY};
    float l [2] = {0.f, 0.f};
    float o_acc[8][4] = {};
    const float CF = SCALE * 1.44269504f;

    for (int t0 = 0; t0 < SPA; t0 += KT) {
        __syncthreads();
        // load K/V tiles: direct [d][key] copies
        #pragma unroll
        for (int r = 0; r < 2; r++) {
            int i = tid + r * 256;
            int dd = i >> 3, k8 = (i & 7) * 8;
            uint4 kv = *reinterpret_cast<const uint4*>(kb + (size_t)dd * SPA + t0 + k8);
            *reinterpret_cast<uint4*>(&Ks[dd * KV_STR + k8]) = kv;
            uint4 vv = *reinterpret_cast<const uint4*>(vb + (size_t)dd * SPA + t0 + k8);
            *reinterpret_cast<uint4*>(&Vs[dd * KV_STR + k8]) = vv;
        }
        __syncthreads();

        // S = Q K^T : M=16, N=64 keys, K=64 d
        float sacc[8][4] = {};
        #pragma unroll
        for (int kk4 = 0; kk4 < 4; kk4++) {
            #pragma unroll
            for (int ntp = 0; ntp < 8; ntp += 2) {
                uint32_t bf[4];
                uint32_t ad = smem_u32(&Ks[(kk4*16 + (lmat & 1)*8 + lrow) * KV_STR
                                           + (ntp + (lmat >> 1))*8]);
                ldsm_x4_t(bf, ad);
                mma_bf16(sacc[ntp],     qa[kk4], bf);
                mma_bf16(sacc[ntp + 1], qa[kk4], bf + 2);
            }
        }

        // online softmax -> P packed bf16 in registers (PV A-fragments)
        uint32_t pp[8][2];
        #pragma unroll
        for (int rh = 0; rh < 2; rh++) {
            float mx = -1e30f;
            #pragma unroll
            for (int nt = 0; nt < 8; nt++)
                mx = fmaxf(mx, fmaxf(sacc[nt][rh*2], sacc[nt][rh*2+1]));
            mx *= CF;
            mx = fmaxf(mx, __shfl_xor_sync(0xffffffffu, mx, 1));
            mx = fmaxf(mx, __shfl_xor_sync(0xffffffffu, mx, 2));
            float mnew = fmaxf(m2[rh], mx);
            float alpha = exp2f(m2[rh] - mnew);
            m2[rh] = mnew;
            float rs = 0.f;
            #pragma unroll
            for (int nt = 0; nt < 8; nt++) {
                float p0 = exp2f(sacc[nt][rh*2]   * CF - mnew);
                float p1 = exp2f(sacc[nt][rh*2+1] * CF - mnew);
                rs += p0 + p1;
                pp[nt][rh] = packbf(p0, p1);
                o_acc[nt][rh*2]   *= alpha;
                o_acc[nt][rh*2+1] *= alpha;
            }
            rs += __shfl_xor_sync(0xffffffffu, rs, 1);
            rs += __shfl_xor_sync(0xffffffffu, rs, 2);
            l[rh] = l[rh] * alpha + rs;
        }

        // O += P V : M=16 q, N=64 d, K=64 keys  (P straight from registers)
        #pragma unroll
        for (int j = 0; j < 4; j++) {
            uint32_t pa[4] = {pp[2*j][0], pp[2*j][1], pp[2*j+1][0], pp[2*j+1][1]};
            #pragma unroll
            for (int dt = 0; dt < 8; dt += 2) {
                uint32_t bv[4];
                uint32_t ad = smem_u32(&Vs[((dt + (lmat >> 1))*8 + lrow) * KV_STR
                                           + j*16 + (lmat & 1)*8]);
                ldsm_x4(bv, ad);
                mma_bf16(o_acc[dt],     pa, bv);
                mma_bf16(o_acc[dt + 1], pa, bv + 2);
            }
        }
    }

    // normalize + write bf16: g_ao[b][h*64+dd][q0+qr]
    __nv_bfloat16* ob = g_ao + ((size_t)b * CH + h * HD) * SPA + q0;
    #pragma unroll
    for (int rh = 0; rh < 2; rh++) {
        float inv = 1.0f / l[rh];
        int qr = w * 16 + rh * 8 + (lane >> 2);
        #pragma unroll
        for (int nt = 0; nt < 8; nt++) {
            int dd = nt * 8 + 2 * (lane & 3);
            ob[(size_t)dd * SPA + qr]       = __float2bfloat16(o_acc[nt][rh*2]   * inv);
            ob[(size_t)(dd + 1) * SPA + qr] = __float2bfloat16(o_acc[nt][rh*2+1] * inv);
        }
    }
}

// ---------------------------------------------------------------------------
extern "C" void kernel_launch(void* const* d_in, const int* in_sizes, int n_in,
                              void* d_out, int out_size) {
    const float* x      = (const float*)d_in[0];
    const float* gamma  = (const float*)d_in[1];
    const float* beta   = (const float*)d_in[2];
    const float* w_qkv  = (const float*)d_in[3];
    const float* b_qkv  = (const float*)d_in[4];
    const float* w_proj = (const float*)d_in[5];
    const float* b_proj = (const float*)d_in[6];
    float* out = (float*)d_out;

    __nv_bfloat16 *xn_p, *qkv_p, *ao_p;
    cudaGetSymbolAddress((void**)&xn_p,  g_xn);
    cudaGetSymbolAddress((void**)&qkv_p, g_qkv);
    cudaGetSymbolAddress((void**)&ao_p,  g_ao);

    // GroupNorm
    k_gn_part <<<BATCH * NGRP * PARTS, 256>>>(x);
    k_gn_final<<<1, 32>>>();
    k_gn_norm <<<(BATCH * CH * SPA) / 4 / 256, 256>>>(x, gamma, beta);

    // QKV GEMM (M = 768), bf16 out
    {
        dim3 grid(SPA / 128, (3 * CH) / 128, BATCH);
        k_gemm<false, __nv_bfloat16><<<grid, 256>>>(w_qkv, b_qkv, xn_p, qkv_p,
                                                    nullptr, 3 * CH);
    }

    // Flash attention
    {
        dim3 grid(SPA / QT, BATCH * NH);
        k_attn<<<grid, 256>>>();
    }

    // Proj GEMM + residual (M = 256), fp32 out
    {
        dim3 grid(SPA / 128, CH / 128, BATCH);
        k_gemm<true, float><<<grid, 256>>>(w_proj, b_proj, ao_p, out, x, CH);
    }
}